// round 4
// baseline (speedup 1.0000x reference)
#include <cuda_runtime.h>
#include <stdint.h>

// Problem constants
#define BSZ  16
#define SEQN 1024
#define NVV  512
#define DMM  256
#define KCL  8

// GEMM tiling
#define KB 32     // k-chunk (over SEQ)
#define VT 64     // v-rows per block

// -------- device scratch (static globals: no allocation allowed) ----------
__device__ float g_cn[KCL * DMM];             // normalized cluster_emb
__device__ float g_soft[BSZ * NVV * KCL];     // prob_temp rows [b*512+v][k]
__device__ float g_bern[KCL * BSZ * NVV];     // bernoulli outcomes, linear idx

typedef unsigned long long ull;

// -------- packed f32x2 helpers --------------------------------------------
__device__ __forceinline__ ull pack2(float x, float y) {
    ull r; asm("mov.b64 %0, {%1, %2};" : "=l"(r) : "f"(x), "f"(y)); return r;
}
__device__ __forceinline__ float2 unpk2(ull a) {
    float2 f; asm("mov.b64 {%0, %1}, %2;" : "=f"(f.x), "=f"(f.y) : "l"(a)); return f;
}
__device__ __forceinline__ void fma2(ull& d, ull a, ull b) {
    asm("fma.rn.f32x2 %0, %1, %2, %0;" : "+l"(d) : "l"(a), "l"(b));
}

// -------- JAX threefry2x32 (key = (0,7)), partitionable 32-bit fold -------
__device__ __forceinline__ uint32_t rotl32(uint32_t x, int r) {
    return (x << r) | (x >> (32 - r));
}
__device__ __forceinline__ uint32_t threefry_bits32(uint32_t c0, uint32_t c1) {
    const uint32_t ks0 = 0u, ks1 = 7u;
    const uint32_t ks2 = ks0 ^ ks1 ^ 0x1BD11BDAu;
    uint32_t x0 = c0 + ks0, x1 = c1 + ks1;
#define TFR(r) { x0 += x1; x1 = rotl32(x1, (r)); x1 ^= x0; }
    TFR(13) TFR(15) TFR(26) TFR(6)   x0 += ks1; x1 += ks2 + 1u;
    TFR(17) TFR(29) TFR(16) TFR(24)  x0 += ks2; x1 += ks0 + 2u;
    TFR(13) TFR(15) TFR(26) TFR(6)   x0 += ks0; x1 += ks1 + 3u;
    TFR(17) TFR(29) TFR(16) TFR(24)  x0 += ks1; x1 += ks2 + 4u;
    TFR(13) TFR(15) TFR(26) TFR(6)   x0 += ks2; x1 += ks0 + 5u;
#undef TFR
    return x0 ^ x1;   // partitionable 32-bit output: bits1 ^ bits2
}

// -------- kernel A: normalize cluster_emb rows ----------------------------
__global__ void prep_cn_kernel(const float* __restrict__ ce) {
    int w = threadIdx.x >> 5;     // warp -> cluster row (8 warps)
    int lane = threadIdx.x & 31;
    const float* row = ce + w * DMM;
    float s = 0.f;
#pragma unroll
    for (int j = 0; j < DMM / 32; ++j) {
        float t = row[lane + j * 32];
        s += t * t;
    }
#pragma unroll
    for (int o = 16; o; o >>= 1) s += __shfl_xor_sync(0xffffffffu, s, o);
    float nrm = fmaxf(sqrtf(s), 1e-12f);
#pragma unroll
    for (int j = 0; j < DMM / 32; ++j)
        g_cn[w * DMM + lane + j * 32] = row[lane + j * 32] / nrm;
}

// -------- kernel B: fp32 GEMM + cosine + sinkhorn, fused ------------------
// Per block: 64 v-rows x all 256 d, K=1024 over SEQ. Each thread: 8v x 8d
// accumulated as 4 f32x2 pairs per v. Epilogue reduces per-v norm + 8 dots
// across the warp (lanes span d), then writes soft = exp(prob/0.05)/sum.
__global__ __launch_bounds__(256, 2)
void gemm_prob_kernel(const float* __restrict__ x, const float* __restrict__ W,
                      const float* __restrict__ bias) {
    __shared__ __align__(16) float As[KB][VT];        // As[s][v]
    __shared__ __align__(16) float Bs[KB][DMM + 2];   // Bs[s][d], pad 2 (2-way max)

    const int b   = blockIdx.y;
    const int v0  = blockIdx.x * VT;
    const int tid = threadIdx.x;
    const int ty  = tid >> 5;   // warp id 0..7 -> v group
    const int tx  = tid & 31;   // lane -> d group (d = tx*8 + j)

    const float* xb = x + (size_t)b * SEQN * NVV;

    ull c2[8][4];
#pragma unroll
    for (int i = 0; i < 8; ++i)
#pragma unroll
        for (int j = 0; j < 4; ++j) c2[i][j] = 0ull;

    for (int s0 = 0; s0 < SEQN; s0 += KB) {
        // A tile: x[b][s0..s0+31][v0..v0+63], coalesced float4
#pragma unroll
        for (int it = 0; it < 2; ++it) {
            int t4 = tid + it * 256;
            int k  = t4 >> 4;
            int vq = t4 & 15;
            float4 a = *(const float4*)(xb + (size_t)(s0 + k) * NVV + v0 + vq * 4);
            *(float4*)&As[k][vq * 4] = a;
        }
        // B tile: W[d][s0+lane] for all 256 d (transposed store into Bs[s][d])
#pragma unroll
        for (int dd = 0; dd < 32; ++dd) {
            int d = dd * 8 + ty;
            Bs[tx][d] = W[d * SEQN + s0 + tx];
        }
        __syncthreads();

#pragma unroll
        for (int k = 0; k < KB; ++k) {
            float4 a01 = *(const float4*)&As[k][ty * 8];
            float4 a23 = *(const float4*)&As[k][ty * 8 + 4];
            const ull* brow = (const ull*)&Bs[k][tx * 8];   // 8B aligned
            ull b0 = brow[0], b1 = brow[1], b2 = brow[2], b3 = brow[3];
            float av[8] = {a01.x, a01.y, a01.z, a01.w, a23.x, a23.y, a23.z, a23.w};
#pragma unroll
            for (int i = 0; i < 8; ++i) {
                ull a2 = pack2(av[i], av[i]);
                fma2(c2[i][0], a2, b0);
                fma2(c2[i][1], a2, b1);
                fma2(c2[i][2], a2, b2);
                fma2(c2[i][3], a2, b3);
            }
        }
        __syncthreads();
    }

    // Stage cn (2048 floats, exactly As size) + bias into smem for epilogue.
    float* cns = &As[0][0];
    float* bss = &Bs[0][0];
    for (int idx = tid; idx < KCL * DMM; idx += 256) cns[idx] = g_cn[idx];
    for (int idx = tid; idx < DMM; idx += 256)       bss[idx] = bias[idx];
    __syncthreads();

#pragma unroll
    for (int i = 0; i < 8; ++i) {
        float y[8];
#pragma unroll
        for (int j2 = 0; j2 < 4; ++j2) {
            float2 p = unpk2(c2[i][j2]);
            y[2 * j2]     = p.x + bss[tx * 8 + 2 * j2];
            y[2 * j2 + 1] = p.y + bss[tx * 8 + 2 * j2 + 1];
        }
        float pn = 0.f;
        float pd[KCL];
#pragma unroll
        for (int kk = 0; kk < KCL; ++kk) {
            const float4* c4 = (const float4*)&cns[kk * DMM + tx * 8];
            float4 p = c4[0], q = c4[1];
            pd[kk] = y[0]*p.x + y[1]*p.y + y[2]*p.z + y[3]*p.w
                   + y[4]*q.x + y[5]*q.y + y[6]*q.z + y[7]*q.w;
        }
#pragma unroll
        for (int j = 0; j < 8; ++j) pn += y[j] * y[j];
#pragma unroll
        for (int o = 16; o; o >>= 1) {
            pn += __shfl_xor_sync(0xffffffffu, pn, o);
#pragma unroll
            for (int kk = 0; kk < KCL; ++kk)
                pd[kk] += __shfl_xor_sync(0xffffffffu, pd[kk], o);
        }
        if (tx == 0) {
            float nrm = fmaxf(sqrtf(pn), 1e-12f);
            float e[KCL];
            float esum = 0.f;
#pragma unroll
            for (int kk = 0; kk < KCL; ++kk) {
                float prob = pd[kk] / nrm;           // cosine similarity
                e[kk] = expf(prob / 0.05f);          // exp(q/EPS), no max-sub (match ref)
                esum += e[kk];
            }
            int v = v0 + ty * 8 + i;
            float* dst = g_soft + ((size_t)(b * NVV + v)) * KCL;
#pragma unroll
            for (int kk = 0; kk < KCL; ++kk) dst[kk] = e[kk] / esum;
        }
    }
}

// -------- kernel C0: bernoulli draws (one thread per (k,b,v)) -------------
__global__ void bern_kernel() {
    int i = blockIdx.x * 256 + threadIdx.x;     // 0..65535, row-major (k,b,v,0)
    uint32_t bits = threefry_bits32(0u, (uint32_t)i);
    float f = __uint_as_float((bits >> 9) | 0x3f800000u) - 1.0f;
    float u = fmaxf(0.0f, f);
    int kk  = i >> 13;      // /(16*512)
    int rem = i & 8191;     // b*512 + v
    float soft = g_soft[rem * KCL + kk];
    g_bern[i] = (u < soft) ? 1.0f : 0.0f;
}

// -------- kernel C1: broadcast write, DRAM-bound --------------------------
// One block per output row; 256 threads x float4 = 4KB contiguous.
__global__ void write_kernel(float4* __restrict__ out) {
    int row = blockIdx.x;                 // 0..65535
    float val = g_bern[row];              // broadcast load (L1)
    float4 v4 = make_float4(val, val, val, val);
    out[(size_t)row * 256 + threadIdx.x] = v4;
}

// -------- launch -----------------------------------------------------------
extern "C" void kernel_launch(void* const* d_in, const int* in_sizes, int n_in,
                              void* d_out, int out_size) {
    // Identify inputs by element count (robust to ordering): x, W, b, cluster_emb
    const float* x = nullptr;
    const float* W = nullptr;
    const float* bias = nullptr;
    const float* ce = nullptr;
    for (int i = 0; i < n_in; ++i) {
        switch (in_sizes[i]) {
            case BSZ * SEQN * NVV: x    = (const float*)d_in[i]; break;  // 8388608
            case DMM * SEQN:       W    = (const float*)d_in[i]; break;  // 262144
            case DMM:              bias = (const float*)d_in[i]; break;  // 256
            case KCL * DMM:        ce   = (const float*)d_in[i]; break;  // 2048
            default: break;
        }
    }
    float4* out = (float4*)d_out;

    prep_cn_kernel<<<1, 256>>>(ce);
    gemm_prob_kernel<<<dim3(NVV / VT, BSZ), 256>>>(x, W, bias);
    bern_kernel<<<(KCL * BSZ * NVV) / 256, 256>>>();
    write_kernel<<<KCL * BSZ * NVV, 256>>>(out);
    (void)out_size;
}

// round 5
// speedup vs baseline: 1.0355x; 1.0355x over previous
#include <cuda_runtime.h>
#include <stdint.h>

// Problem constants
#define BSZ  16
#define SEQN 1024
#define NVV  512
#define DMM  256
#define KCL  8

// GEMM tiling
#define KB 16     // k-chunk (over SEQ)
#define VT 64     // v-rows per block
#define BPAD (DMM + 4)   // Bs row stride in floats (1040B -> 16B aligned rows)

// -------- device scratch (static globals: no allocation allowed) ----------
__device__ float g_cn[KCL * DMM];             // normalized cluster_emb
__device__ float g_soft[BSZ * NVV * KCL];     // prob_temp rows [b*512+v][k]
__device__ float g_bern[KCL * BSZ * NVV];     // bernoulli outcomes, linear idx

typedef unsigned long long ull;

// -------- packed f32x2 helpers --------------------------------------------
__device__ __forceinline__ ull pack2(float x, float y) {
    ull r; asm("mov.b64 %0, {%1, %2};" : "=l"(r) : "f"(x), "f"(y)); return r;
}
__device__ __forceinline__ float2 unpk2(ull a) {
    float2 f; asm("mov.b64 {%0, %1}, %2;" : "=f"(f.x), "=f"(f.y) : "l"(a)); return f;
}
__device__ __forceinline__ void fma2(ull& d, ull a, ull b) {
    asm("fma.rn.f32x2 %0, %1, %2, %0;" : "+l"(d) : "l"(a), "l"(b));
}

// -------- JAX threefry2x32 (key = (0,7)), partitionable 32-bit fold -------
__device__ __forceinline__ uint32_t rotl32(uint32_t x, int r) {
    return (x << r) | (x >> (32 - r));
}
__device__ __forceinline__ uint32_t threefry_bits32(uint32_t c0, uint32_t c1) {
    const uint32_t ks0 = 0u, ks1 = 7u;
    const uint32_t ks2 = ks0 ^ ks1 ^ 0x1BD11BDAu;
    uint32_t x0 = c0 + ks0, x1 = c1 + ks1;
#define TFR(r) { x0 += x1; x1 = rotl32(x1, (r)); x1 ^= x0; }
    TFR(13) TFR(15) TFR(26) TFR(6)   x0 += ks1; x1 += ks2 + 1u;
    TFR(17) TFR(29) TFR(16) TFR(24)  x0 += ks2; x1 += ks0 + 2u;
    TFR(13) TFR(15) TFR(26) TFR(6)   x0 += ks0; x1 += ks1 + 3u;
    TFR(17) TFR(29) TFR(16) TFR(24)  x0 += ks1; x1 += ks2 + 4u;
    TFR(13) TFR(15) TFR(26) TFR(6)   x0 += ks2; x1 += ks0 + 5u;
#undef TFR
    return x0 ^ x1;
}

// -------- kernel A: normalize cluster_emb rows ----------------------------
__global__ void prep_cn_kernel(const float* __restrict__ ce) {
    int w = threadIdx.x >> 5;
    int lane = threadIdx.x & 31;
    const float* row = ce + w * DMM;
    float s = 0.f;
#pragma unroll
    for (int j = 0; j < DMM / 32; ++j) {
        float t = row[lane + j * 32];
        s += t * t;
    }
#pragma unroll
    for (int o = 16; o; o >>= 1) s += __shfl_xor_sync(0xffffffffu, s, o);
    float nrm = fmaxf(sqrtf(s), 1e-12f);
#pragma unroll
    for (int j = 0; j < DMM / 32; ++j)
        g_cn[w * DMM + lane + j * 32] = row[lane + j * 32] / nrm;
}

// -------- kernel B: fp32 GEMM + cosine + sinkhorn, fused ------------------
// 512 threads, 16 warps (4/SMSP). Block: 64 v-rows x 256 d, K=1024.
// Thread tile 8v x 4d. A values pre-duplicated in smem as packed f32x2.
// Double-buffered global staging through registers.
__global__ __launch_bounds__(512, 1)
void gemm_prob_kernel(const float* __restrict__ x, const float* __restrict__ W,
                      const float* __restrict__ bias) {
    __shared__ __align__(16) ull   As2[KB][VT];    // 8 KB, duplicated a
    __shared__ __align__(16) float Bs[KB][BPAD];   // 16.64 KB

    const int b   = blockIdx.y;
    const int v0  = blockIdx.x * VT;
    const int tid = threadIdx.x;
    const int w   = tid >> 5;
    const int lane = tid & 31;
    const int vg   = w & 7;        // v-group 0..7
    const int half = w >> 3;       // d-half 0..1
    const int dbase = half * 128 + lane * 4;

    const float* xb = x + (size_t)b * SEQN * NVV;

    // load roles
    const int xk = tid >> 4, xv = tid & 15;        // x tile: tid<256 only
    const int wd = tid & 255, wsh = tid >> 8;      // W tile: all 512

    ull c2[8][2];
#pragma unroll
    for (int i = 0; i < 8; ++i) { c2[i][0] = 0ull; c2[i][1] = 0ull; }

    // prefetch chunk 0
    float4 xa = make_float4(0.f, 0.f, 0.f, 0.f);
    if (tid < 256)
        xa = *(const float4*)(xb + (size_t)xk * NVV + v0 + xv * 4);
    float4 wa0 = *(const float4*)(W + (size_t)wd * SEQN + wsh * 8);
    float4 wa1 = *(const float4*)(W + (size_t)wd * SEQN + wsh * 8 + 4);

    for (int s0 = 0; s0 < SEQN; s0 += KB) {
        __syncthreads();
        // commit staged tiles to smem
        if (tid < 256) {
            As2[xk][xv * 4 + 0] = pack2(xa.x, xa.x);
            As2[xk][xv * 4 + 1] = pack2(xa.y, xa.y);
            As2[xk][xv * 4 + 2] = pack2(xa.z, xa.z);
            As2[xk][xv * 4 + 3] = pack2(xa.w, xa.w);
        }
        {
            int sb = wsh * 8;
            Bs[sb + 0][wd] = wa0.x; Bs[sb + 1][wd] = wa0.y;
            Bs[sb + 2][wd] = wa0.z; Bs[sb + 3][wd] = wa0.w;
            Bs[sb + 4][wd] = wa1.x; Bs[sb + 5][wd] = wa1.y;
            Bs[sb + 6][wd] = wa1.z; Bs[sb + 7][wd] = wa1.w;
        }
        __syncthreads();

        // prefetch next chunk (latency overlapped with compute below)
        int sn = s0 + KB;
        if (sn < SEQN) {
            if (tid < 256)
                xa = *(const float4*)(xb + (size_t)(sn + xk) * NVV + v0 + xv * 4);
            wa0 = *(const float4*)(W + (size_t)wd * SEQN + sn + wsh * 8);
            wa1 = *(const float4*)(W + (size_t)wd * SEQN + sn + wsh * 8 + 4);
        }

#pragma unroll
        for (int k = 0; k < KB; ++k) {
            ulonglong2 bb = *(const ulonglong2*)&Bs[k][dbase];
            const ull* ap = &As2[k][vg * 8];
#pragma unroll
            for (int i = 0; i < 8; ++i) {
                ull a = ap[i];            // LDS.64, warp-broadcast
                fma2(c2[i][0], a, bb.x);
                fma2(c2[i][1], a, bb.y);
            }
        }
    }

    // ---- epilogue: cosine + sinkhorn ----
    __syncthreads();
    float* sc  = &Bs[0][0];          // stage cn (2048) + bias (256)
    float* red = (float*)&As2[0][0]; // 2*64*9 partials
    for (int idx = tid; idx < KCL * DMM; idx += 512) sc[idx] = g_cn[idx];
    if (tid < DMM) sc[KCL * DMM + tid] = bias[tid];
    __syncthreads();

#pragma unroll
    for (int i = 0; i < 8; ++i) {
        float2 p0 = unpk2(c2[i][0]);
        float2 p1 = unpk2(c2[i][1]);
        float y0 = p0.x + sc[KCL * DMM + dbase + 0];
        float y1 = p0.y + sc[KCL * DMM + dbase + 1];
        float y2 = p1.x + sc[KCL * DMM + dbase + 2];
        float y3 = p1.y + sc[KCL * DMM + dbase + 3];

        float r[9];
        r[0] = y0 * y0 + y1 * y1 + y2 * y2 + y3 * y3;   // norm partial
#pragma unroll
        for (int kk = 0; kk < KCL; ++kk) {
            const float4 c = *(const float4*)&sc[kk * DMM + dbase];
            r[1 + kk] = y0 * c.x + y1 * c.y + y2 * c.z + y3 * c.w;
        }
#pragma unroll
        for (int o = 16; o; o >>= 1) {
#pragma unroll
            for (int j = 0; j < 9; ++j)
                r[j] += __shfl_xor_sync(0xffffffffu, r[j], o);
        }
        if (lane == 0) {
            int base = (half * VT + vg * 8 + i) * 9;
#pragma unroll
            for (int j = 0; j < 9; ++j) red[base + j] = r[j];
        }
    }
    __syncthreads();

    if (tid < VT) {
        float pn = red[tid * 9] + red[(VT + tid) * 9];
        float nrm = fmaxf(sqrtf(pn), 1e-12f);
        float e[KCL];
        float esum = 0.f;
#pragma unroll
        for (int kk = 0; kk < KCL; ++kk) {
            float pd = red[tid * 9 + 1 + kk] + red[(VT + tid) * 9 + 1 + kk];
            float prob = pd / nrm;
            e[kk] = expf(prob / 0.05f);
            esum += e[kk];
        }
        float* dst = g_soft + ((size_t)(b * NVV + v0 + tid)) * KCL;
#pragma unroll
        for (int kk = 0; kk < KCL; ++kk) dst[kk] = e[kk] / esum;
    }
}

// -------- kernel C0: bernoulli draws (one thread per (k,b,v)) -------------
__global__ void bern_kernel() {
    int i = blockIdx.x * 256 + threadIdx.x;     // 0..65535, row-major (k,b,v,0)
    uint32_t bits = threefry_bits32(0u, (uint32_t)i);
    float f = __uint_as_float((bits >> 9) | 0x3f800000u) - 1.0f;
    float u = fmaxf(0.0f, f);
    int kk  = i >> 13;      // /(16*512)
    int rem = i & 8191;     // b*512 + v
    float soft = g_soft[rem * KCL + kk];
    g_bern[i] = (u < soft) ? 1.0f : 0.0f;
}

// -------- kernel C1: broadcast write, DRAM-bound --------------------------
// 2048 blocks x 32 contiguous rows: each block streams 128KB contiguous.
#define ROWS_PER_BLK 32
__global__ __launch_bounds__(256, 8)
void write_kernel(float4* __restrict__ out) {
    __shared__ float vals[ROWS_PER_BLK];
    int rowbase = blockIdx.x * ROWS_PER_BLK;
    if (threadIdx.x < ROWS_PER_BLK)
        vals[threadIdx.x] = g_bern[rowbase + threadIdx.x];
    __syncthreads();
    float4* o = out + (size_t)rowbase * 256 + threadIdx.x;
#pragma unroll
    for (int i = 0; i < ROWS_PER_BLK; ++i) {
        float v = vals[i];
        o[(size_t)i * 256] = make_float4(v, v, v, v);
    }
}

// -------- launch -----------------------------------------------------------
extern "C" void kernel_launch(void* const* d_in, const int* in_sizes, int n_in,
                              void* d_out, int out_size) {
    const float* x = nullptr;
    const float* W = nullptr;
    const float* bias = nullptr;
    const float* ce = nullptr;
    for (int i = 0; i < n_in; ++i) {
        switch (in_sizes[i]) {
            case BSZ * SEQN * NVV: x    = (const float*)d_in[i]; break;
            case DMM * SEQN:       W    = (const float*)d_in[i]; break;
            case DMM:              bias = (const float*)d_in[i]; break;
            case KCL * DMM:        ce   = (const float*)d_in[i]; break;
            default: break;
        }
    }
    float4* out = (float4*)d_out;

    prep_cn_kernel<<<1, 256>>>(ce);
    gemm_prob_kernel<<<dim3(NVV / VT, BSZ), 512>>>(x, W, bias);
    bern_kernel<<<(KCL * BSZ * NVV) / 256, 256>>>();
    write_kernel<<<(KCL * BSZ * NVV) / ROWS_PER_BLK, 256>>>(out);
    (void)out_size;
}

// round 6
// speedup vs baseline: 1.2511x; 1.2082x over previous
#include <cuda_runtime.h>
#include <stdint.h>

// Problem constants
#define BSZ  16
#define SEQN 1024
#define NVV  512
#define DMM  256
#define KCL  8

// GEMM tiling
#define KB 16                 // k-chunk (over SEQ)
#define VT 64                 // v-rows per block
#define NCHUNK (SEQN / KB)    // 64

// -------- device scratch ---------------------------------------------------
__device__ float g_cn[KCL * DMM];             // normalized cluster_emb
__device__ float g_soft[BSZ * NVV * KCL];     // prob_temp rows [b*512+v][k]

typedef unsigned long long ull;

// -------- packed f32x2 helpers --------------------------------------------
__device__ __forceinline__ ull pack2(float x, float y) {
    ull r; asm("mov.b64 %0, {%1, %2};" : "=l"(r) : "f"(x), "f"(y)); return r;
}
__device__ __forceinline__ float2 unpk2(ull a) {
    float2 f; asm("mov.b64 {%0, %1}, %2;" : "=f"(f.x), "=f"(f.y) : "l"(a)); return f;
}
__device__ __forceinline__ void fma2(ull& d, ull a, ull b) {
    asm("fma.rn.f32x2 %0, %1, %2, %0;" : "+l"(d) : "l"(a), "l"(b));
}

// -------- JAX threefry2x32 (key = (0,7)), partitionable 32-bit fold -------
__device__ __forceinline__ uint32_t rotl32(uint32_t x, int r) {
    return (x << r) | (x >> (32 - r));
}
__device__ __forceinline__ uint32_t threefry_bits32(uint32_t c0, uint32_t c1) {
    const uint32_t ks0 = 0u, ks1 = 7u;
    const uint32_t ks2 = ks0 ^ ks1 ^ 0x1BD11BDAu;
    uint32_t x0 = c0 + ks0, x1 = c1 + ks1;
#define TFR(r) { x0 += x1; x1 = rotl32(x1, (r)); x1 ^= x0; }
    TFR(13) TFR(15) TFR(26) TFR(6)   x0 += ks1; x1 += ks2 + 1u;
    TFR(17) TFR(29) TFR(16) TFR(24)  x0 += ks2; x1 += ks0 + 2u;
    TFR(13) TFR(15) TFR(26) TFR(6)   x0 += ks0; x1 += ks1 + 3u;
    TFR(17) TFR(29) TFR(16) TFR(24)  x0 += ks1; x1 += ks2 + 4u;
    TFR(13) TFR(15) TFR(26) TFR(6)   x0 += ks2; x1 += ks0 + 5u;
#undef TFR
    return x0 ^ x1;
}

// -------- kernel A: normalize cluster_emb rows ----------------------------
__global__ void prep_cn_kernel(const float* __restrict__ ce) {
    int w = threadIdx.x >> 5;
    int lane = threadIdx.x & 31;
    const float* row = ce + w * DMM;
    float s = 0.f;
#pragma unroll
    for (int j = 0; j < DMM / 32; ++j) {
        float t = row[lane + j * 32];
        s += t * t;
    }
#pragma unroll
    for (int o = 16; o; o >>= 1) s += __shfl_xor_sync(0xffffffffu, s, o);
    float nrm = fmaxf(sqrtf(s), 1e-12f);
#pragma unroll
    for (int j = 0; j < DMM / 32; ++j)
        g_cn[w * DMM + lane + j * 32] = row[lane + j * 32] / nrm;
}

// -------- kernel B: fp32 GEMM + cosine + sinkhorn, fused ------------------
// 512 threads / 16 warps. Block tile: 64v x 256d, K=1024.
// Warp tile: 32v x 32d (vpanel = w>>3, dpanel = w&7).
// Thread tile: 4v x 8d (vl = lane&7 -> v chunk, dl = lane>>3 -> d chunk).
// Double-buffered smem, 1 sync per chunk. Crossbar ~4 phases/warp/k.
__global__ __launch_bounds__(512, 1)
void gemm_prob_kernel(const float* __restrict__ x, const float* __restrict__ W,
                      const float* __restrict__ bias) {
    __shared__ __align__(16) float As[2][KB][VT];     // 8 KB
    __shared__ __align__(16) float Bs[2][KB][DMM];    // 32 KB (1KB rows, aligned)

    const int b    = blockIdx.y;
    const int v0   = blockIdx.x * VT;
    const int tid  = threadIdx.x;
    const int w    = tid >> 5;
    const int lane = tid & 31;
    const int vpanel = w >> 3;            // 0..1
    const int dpanel = w & 7;             // 0..7
    const int vl = lane & 7;              // 0..7
    const int dl = lane >> 3;             // 0..3
    const int vbase = vpanel * 32 + vl * 4;       // thread's 4 v
    const int dbase = dpanel * 32 + dl * 8;       // thread's 8 d

    const float* xb = x + (size_t)b * SEQN * NVV;

    // load roles
    const int xk = tid >> 4, xv = tid & 15;       // x tile: tid<256
    const int wd = tid & 255, wsh = tid >> 8;     // W tile: all 512

    ull c2[4][4];
#pragma unroll
    for (int i = 0; i < 4; ++i)
#pragma unroll
        for (int j = 0; j < 4; ++j) c2[i][j] = 0ull;

    // prefetch chunk 0
    float4 xa = make_float4(0.f, 0.f, 0.f, 0.f);
    if (tid < 256)
        xa = *(const float4*)(xb + (size_t)xk * NVV + v0 + xv * 4);
    float4 wa0 = *(const float4*)(W + (size_t)wd * SEQN + wsh * 8);
    float4 wa1 = *(const float4*)(W + (size_t)wd * SEQN + wsh * 8 + 4);

    // commit chunk 0 into buffer 0
    if (tid < 256) *(float4*)&As[0][xk][xv * 4] = xa;
    {
        int sb = wsh * 8;
        Bs[0][sb + 0][wd] = wa0.x; Bs[0][sb + 1][wd] = wa0.y;
        Bs[0][sb + 2][wd] = wa0.z; Bs[0][sb + 3][wd] = wa0.w;
        Bs[0][sb + 4][wd] = wa1.x; Bs[0][sb + 5][wd] = wa1.y;
        Bs[0][sb + 6][wd] = wa1.z; Bs[0][sb + 7][wd] = wa1.w;
    }
    __syncthreads();

    for (int c = 0; c < NCHUNK; ++c) {
        const int cur = c & 1;
        const int nxt = cur ^ 1;
        const int sn = (c + 1) * KB;
        if (sn < SEQN) {                      // prefetch next chunk
            if (tid < 256)
                xa = *(const float4*)(xb + (size_t)(sn + xk) * NVV + v0 + xv * 4);
            wa0 = *(const float4*)(W + (size_t)wd * SEQN + sn + wsh * 8);
            wa1 = *(const float4*)(W + (size_t)wd * SEQN + sn + wsh * 8 + 4);
        }

#pragma unroll
        for (int k = 0; k < KB; ++k) {
            float4 av = *(const float4*)&As[cur][k][vbase];           // 1 phase
            ulonglong2 b01 = *(const ulonglong2*)&Bs[cur][k][dbase];  // 1 phase
            ulonglong2 b23 = *(const ulonglong2*)&Bs[cur][k][dbase + 4];
            ull a0 = pack2(av.x, av.x);
            ull a1 = pack2(av.y, av.y);
            ull a2 = pack2(av.z, av.z);
            ull a3 = pack2(av.w, av.w);
            fma2(c2[0][0], a0, b01.x); fma2(c2[0][1], a0, b01.y);
            fma2(c2[0][2], a0, b23.x); fma2(c2[0][3], a0, b23.y);
            fma2(c2[1][0], a1, b01.x); fma2(c2[1][1], a1, b01.y);
            fma2(c2[1][2], a1, b23.x); fma2(c2[1][3], a1, b23.y);
            fma2(c2[2][0], a2, b01.x); fma2(c2[2][1], a2, b01.y);
            fma2(c2[2][2], a2, b23.x); fma2(c2[2][3], a2, b23.y);
            fma2(c2[3][0], a3, b01.x); fma2(c2[3][1], a3, b01.y);
            fma2(c2[3][2], a3, b23.x); fma2(c2[3][3], a3, b23.y);
        }

        if (sn < SEQN) {
            // smem[nxt] was last read in chunk c-1; the sync at the end of
            // that chunk guarantees it is free to overwrite.
            if (tid < 256) *(float4*)&As[nxt][xk][xv * 4] = xa;
            int sb = wsh * 8;
            Bs[nxt][sb + 0][wd] = wa0.x; Bs[nxt][sb + 1][wd] = wa0.y;
            Bs[nxt][sb + 2][wd] = wa0.z; Bs[nxt][sb + 3][wd] = wa0.w;
            Bs[nxt][sb + 4][wd] = wa1.x; Bs[nxt][sb + 5][wd] = wa1.y;
            Bs[nxt][sb + 6][wd] = wa1.z; Bs[nxt][sb + 7][wd] = wa1.w;
            __syncthreads();
        }
    }

    // ---- epilogue: bias + cosine + sinkhorn ----
    __syncthreads();
    float* sc  = &Bs[0][0][0];        // cn (2048 floats) + bias (256)
    float* red = &As[0][0][0];        // 16 warps x 32 v x 9 = 4608 floats? (>2048)
    // red needs 16*32*9 = 4608 floats = 18KB; As region is only 8KB, so put
    // red after cn+bias inside the Bs region (32KB total: 2304 + 4608 fits).
    red = sc + KCL * DMM + DMM;
    for (int idx = tid; idx < KCL * DMM; idx += 512) sc[idx] = g_cn[idx];
    if (tid < DMM) sc[KCL * DMM + tid] = bias[tid];
    __syncthreads();

    const float* bias_s = sc + KCL * DMM;
#pragma unroll
    for (int i = 0; i < 4; ++i) {     // 4 v per thread
        float y[8];
#pragma unroll
        for (int j = 0; j < 4; ++j) {
            float2 p = unpk2(c2[i][j]);
            y[2 * j]     = p.x + bias_s[dbase + 2 * j];
            y[2 * j + 1] = p.y + bias_s[dbase + 2 * j + 1];
        }
        float r[9];
        r[0] = 0.f;
#pragma unroll
        for (int j = 0; j < 8; ++j) r[0] += y[j] * y[j];
#pragma unroll
        for (int kk = 0; kk < KCL; ++kk) {
            const float* cp = &sc[kk * DMM + dbase];
            float s = 0.f;
#pragma unroll
            for (int j = 0; j < 8; ++j) s += y[j] * cp[j];
            r[1 + kk] = s;
        }
        // reduce across dl (lane bits 3,4)
#pragma unroll
        for (int o = 8; o <= 16; o <<= 1) {
#pragma unroll
            for (int j = 0; j < 9; ++j)
                r[j] += __shfl_xor_sync(0xffffffffu, r[j], o);
        }
        if (dl == 0) {
            float* dst = red + ((size_t)w * 32 + vl * 4 + i) * 9;
#pragma unroll
            for (int j = 0; j < 9; ++j) dst[j] = r[j];
        }
    }
    __syncthreads();

    if (tid < VT) {
        int vp = tid >> 5;            // which vpanel
        int vv = tid & 31;            // v within panel
        float acc[9];
#pragma unroll
        for (int j = 0; j < 9; ++j) acc[j] = 0.f;
#pragma unroll
        for (int p = 0; p < 8; ++p) {
            const float* src = red + ((size_t)(vp * 8 + p) * 32 + vv) * 9;
#pragma unroll
            for (int j = 0; j < 9; ++j) acc[j] += src[j];
        }
        float nrm = fmaxf(sqrtf(acc[0]), 1e-12f);
        float e[KCL];
        float esum = 0.f;
#pragma unroll
        for (int kk = 0; kk < KCL; ++kk) {
            float prob = acc[1 + kk] / nrm;
            e[kk] = expf(prob / 0.05f);
            esum += e[kk];
        }
        float* dst = g_soft + ((size_t)(b * NVV + v0 + tid)) * KCL;
#pragma unroll
        for (int kk = 0; kk < KCL; ++kk) dst[kk] = e[kk] / esum;
    }
}

// -------- kernel C: fused bernoulli + broadcast write ---------------------
// 2048 blocks x 32 contiguous rows (128KB contiguous stream per block).
// First 32 threads draw the bernoulli for their row; streaming stores.
#define ROWS_PER_BLK 32
__global__ __launch_bounds__(256, 8)
void write_kernel(float4* __restrict__ out) {
    __shared__ float vals[ROWS_PER_BLK];
    int rowbase = blockIdx.x * ROWS_PER_BLK;
    if (threadIdx.x < ROWS_PER_BLK) {
        int r = rowbase + threadIdx.x;             // (k,b,v) linear
        uint32_t bits = threefry_bits32(0u, (uint32_t)r);
        float f = __uint_as_float((bits >> 9) | 0x3f800000u) - 1.0f;
        float u = fmaxf(0.0f, f);
        int kk  = r >> 13;
        int rem = r & 8191;                        // b*512 + v
        vals[threadIdx.x] = (u < g_soft[rem * KCL + kk]) ? 1.0f : 0.0f;
    }
    __syncthreads();
    float4* o = out + (size_t)rowbase * 256 + threadIdx.x;
#pragma unroll
    for (int i = 0; i < ROWS_PER_BLK; ++i) {
        float v = vals[i];
        __stcs(&o[(size_t)i * 256], make_float4(v, v, v, v));
    }
}

// -------- launch -----------------------------------------------------------
extern "C" void kernel_launch(void* const* d_in, const int* in_sizes, int n_in,
                              void* d_out, int out_size) {
    const float* x = nullptr;
    const float* W = nullptr;
    const float* bias = nullptr;
    const float* ce = nullptr;
    for (int i = 0; i < n_in; ++i) {
        switch (in_sizes[i]) {
            case BSZ * SEQN * NVV: x    = (const float*)d_in[i]; break;
            case DMM * SEQN:       W    = (const float*)d_in[i]; break;
            case DMM:              bias = (const float*)d_in[i]; break;
            case KCL * DMM:        ce   = (const float*)d_in[i]; break;
            default: break;
        }
    }
    float4* out = (float4*)d_out;

    prep_cn_kernel<<<1, 256>>>(ce);
    gemm_prob_kernel<<<dim3(NVV / VT, BSZ), 512>>>(x, W, bias);
    write_kernel<<<(KCL * BSZ * NVV) / ROWS_PER_BLK, 256>>>(out);
    (void)out_size;
}

// round 8
// speedup vs baseline: 1.3810x; 1.1038x over previous
#include <cuda_runtime.h>
#include <stdint.h>

// Problem constants
#define BSZ  16
#define SEQN 1024
#define NVV  512
#define DMM  256
#define KCL  8

// GEMM tiling
#define KB 16                 // k-chunk (over SEQ)
#define VT 64                 // v-rows per block
#define NCHUNK (SEQN / KB)    // 64

// -------- device scratch ---------------------------------------------------
__device__ float g_soft[BSZ * NVV * KCL];     // prob_temp rows [b*512+v][k]

typedef unsigned long long ull;

// -------- packed f32x2 helpers --------------------------------------------
__device__ __forceinline__ ull pack2(float x, float y) {
    ull r; asm("mov.b64 %0, {%1, %2};" : "=l"(r) : "f"(x), "f"(y)); return r;
}
__device__ __forceinline__ float2 unpk2(ull a) {
    float2 f; asm("mov.b64 {%0, %1}, %2;" : "=f"(f.x), "=f"(f.y) : "l"(a)); return f;
}
__device__ __forceinline__ void fma2(ull& d, ull a, ull b) {
    asm("fma.rn.f32x2 %0, %1, %2, %0;" : "+l"(d) : "l"(a), "l"(b));
}

// -------- JAX threefry2x32 (key = (0,7)), partitionable 32-bit fold -------
__device__ __forceinline__ uint32_t rotl32(uint32_t x, int r) {
    return (x << r) | (x >> (32 - r));
}
__device__ __forceinline__ uint32_t threefry_bits32(uint32_t c0, uint32_t c1) {
    const uint32_t ks0 = 0u, ks1 = 7u;
    const uint32_t ks2 = ks0 ^ ks1 ^ 0x1BD11BDAu;
    uint32_t x0 = c0 + ks0, x1 = c1 + ks1;
#define TFR(r) { x0 += x1; x1 = rotl32(x1, (r)); x1 ^= x0; }
    TFR(13) TFR(15) TFR(26) TFR(6)   x0 += ks1; x1 += ks2 + 1u;
    TFR(17) TFR(29) TFR(16) TFR(24)  x0 += ks2; x1 += ks0 + 2u;
    TFR(13) TFR(15) TFR(26) TFR(6)   x0 += ks0; x1 += ks1 + 3u;
    TFR(17) TFR(29) TFR(16) TFR(24)  x0 += ks1; x1 += ks2 + 4u;
    TFR(13) TFR(15) TFR(26) TFR(6)   x0 += ks2; x1 += ks0 + 5u;
#undef TFR
    return x0 ^ x1;
}

// -------- kernel B: fp32 GEMM + cosine + sinkhorn, fused ------------------
// 256 threads / 8 warps, 2 blocks/SM. Block tile: 64v x 256d (full d), K=1024.
// Warp tile: 32v x 64d (vpanel = w&1, dpanel = w>>1).
// Thread tile: 8v x 8d (vl = lane&3, dl = lane>>2).
// LDS per warp per k: 2x LDS.128 A (4x16B distinct, bcast) + 2x LDS.128 B
// (8x16B distinct, bcast) = 4 phases per 64 FMA -> crossbar has 1.5x headroom.
__global__ __launch_bounds__(256, 2)
void gemm_prob_kernel(const float* __restrict__ x, const float* __restrict__ W,
                      const float* __restrict__ bias,
                      const float* __restrict__ ce) {
    __shared__ __align__(16) float As[2][KB][VT];     // 8 KB
    __shared__ __align__(16) float Bs[2][KB][DMM];    // 32 KB (1KB rows)

    const int b    = blockIdx.y;
    const int v0   = blockIdx.x * VT;
    const int tid  = threadIdx.x;
    const int w    = tid >> 5;
    const int lane = tid & 31;
    const int vpanel = w & 1;             // 0..1
    const int dpanel = w >> 1;            // 0..3
    const int vl = lane & 3;              // 0..3
    const int dl = lane >> 2;             // 0..7
    const int vbase = vpanel * 32 + vl * 8;       // thread's 8 v
    const int dbase = dpanel * 64 + dl * 8;       // thread's 8 d

    const float* xb = x + (size_t)b * SEQN * NVV;

    // load roles: x tile 16k x 64v = 256 float4 (1/thread); W: d = tid, 16 s
    const int xk = tid >> 4, xv = tid & 15;

    ull c2[8][4];
#pragma unroll
    for (int i = 0; i < 8; ++i)
#pragma unroll
        for (int j = 0; j < 4; ++j) c2[i][j] = 0ull;

    // prefetch chunk 0
    float4 xa = *(const float4*)(xb + (size_t)xk * NVV + v0 + xv * 4);
    float4 wa0 = *(const float4*)(W + (size_t)tid * SEQN + 0);
    float4 wa1 = *(const float4*)(W + (size_t)tid * SEQN + 4);
    float4 wa2 = *(const float4*)(W + (size_t)tid * SEQN + 8);
    float4 wa3 = *(const float4*)(W + (size_t)tid * SEQN + 12);

    // commit chunk 0 into buffer 0
    *(float4*)&As[0][xk][xv * 4] = xa;
    Bs[0][0][tid]  = wa0.x; Bs[0][1][tid]  = wa0.y;
    Bs[0][2][tid]  = wa0.z; Bs[0][3][tid]  = wa0.w;
    Bs[0][4][tid]  = wa1.x; Bs[0][5][tid]  = wa1.y;
    Bs[0][6][tid]  = wa1.z; Bs[0][7][tid]  = wa1.w;
    Bs[0][8][tid]  = wa2.x; Bs[0][9][tid]  = wa2.y;
    Bs[0][10][tid] = wa2.z; Bs[0][11][tid] = wa2.w;
    Bs[0][12][tid] = wa3.x; Bs[0][13][tid] = wa3.y;
    Bs[0][14][tid] = wa3.z; Bs[0][15][tid] = wa3.w;
    __syncthreads();

    for (int c = 0; c < NCHUNK; ++c) {
        const int cur = c & 1;
        const int nxt = cur ^ 1;
        const int sn = (c + 1) * KB;
        if (sn < SEQN) {                      // prefetch next chunk
            xa  = *(const float4*)(xb + (size_t)(sn + xk) * NVV + v0 + xv * 4);
            wa0 = *(const float4*)(W + (size_t)tid * SEQN + sn + 0);
            wa1 = *(const float4*)(W + (size_t)tid * SEQN + sn + 4);
            wa2 = *(const float4*)(W + (size_t)tid * SEQN + sn + 8);
            wa3 = *(const float4*)(W + (size_t)tid * SEQN + sn + 12);
        }

#pragma unroll
        for (int k = 0; k < KB; ++k) {
            float4 a0 = *(const float4*)&As[cur][k][vbase];
            float4 a1 = *(const float4*)&As[cur][k][vbase + 4];
            ulonglong2 b01 = *(const ulonglong2*)&Bs[cur][k][dbase];
            ulonglong2 b23 = *(const ulonglong2*)&Bs[cur][k][dbase + 4];
            float av[8] = {a0.x, a0.y, a0.z, a0.w, a1.x, a1.y, a1.z, a1.w};
#pragma unroll
            for (int i = 0; i < 8; ++i) {
                ull a = pack2(av[i], av[i]);
                fma2(c2[i][0], a, b01.x);
                fma2(c2[i][1], a, b01.y);
                fma2(c2[i][2], a, b23.x);
                fma2(c2[i][3], a, b23.y);
            }
        }

        if (sn < SEQN) {
            *(float4*)&As[nxt][xk][xv * 4] = xa;
            Bs[nxt][0][tid]  = wa0.x; Bs[nxt][1][tid]  = wa0.y;
            Bs[nxt][2][tid]  = wa0.z; Bs[nxt][3][tid]  = wa0.w;
            Bs[nxt][4][tid]  = wa1.x; Bs[nxt][5][tid]  = wa1.y;
            Bs[nxt][6][tid]  = wa1.z; Bs[nxt][7][tid]  = wa1.w;
            Bs[nxt][8][tid]  = wa2.x; Bs[nxt][9][tid]  = wa2.y;
            Bs[nxt][10][tid] = wa2.z; Bs[nxt][11][tid] = wa2.w;
            Bs[nxt][12][tid] = wa3.x; Bs[nxt][13][tid] = wa3.y;
            Bs[nxt][14][tid] = wa3.z; Bs[nxt][15][tid] = wa3.w;
            __syncthreads();
        }
    }

    // ---- epilogue: cn normalize + bias + cosine + sinkhorn ----
    __syncthreads();
    float* cn_s   = &Bs[0][0][0];              // 8 x 256 floats
    float* bias_s = cn_s + KCL * DMM;          // 256
    float* red    = bias_s + DMM;              // 4 dpanels x 64 v x 9 = 2304
    // (total 4608 floats = 18 KB, fits in Bs' 32 KB)

    // normalize cluster_emb rows: warp w handles row w (8 warps, 8 rows)
    {
        const float* row = ce + w * DMM;
        float s = 0.f;
#pragma unroll
        for (int j = 0; j < DMM / 32; ++j) {
            float t = row[lane + j * 32];
            s += t * t;
        }
#pragma unroll
        for (int o = 16; o; o >>= 1) s += __shfl_xor_sync(0xffffffffu, s, o);
        float nrm = fmaxf(sqrtf(s), 1e-12f);
#pragma unroll
        for (int j = 0; j < DMM / 32; ++j)
            cn_s[w * DMM + lane + j * 32] = row[lane + j * 32] / nrm;
    }
    bias_s[tid] = bias[tid];
    __syncthreads();

#pragma unroll
    for (int i = 0; i < 8; ++i) {     // 8 v per thread
        float y[8];
#pragma unroll
        for (int j = 0; j < 4; ++j) {
            float2 p = unpk2(c2[i][j]);
            y[2 * j]     = p.x + bias_s[dbase + 2 * j];
            y[2 * j + 1] = p.y + bias_s[dbase + 2 * j + 1];
        }
        float r[9];
        r[0] = 0.f;
#pragma unroll
        for (int j = 0; j < 8; ++j) r[0] += y[j] * y[j];
#pragma unroll
        for (int kk = 0; kk < KCL; ++kk) {
            const float* cp = &cn_s[kk * DMM + dbase];
            float s = 0.f;
#pragma unroll
            for (int j = 0; j < 8; ++j) s += y[j] * cp[j];
            r[1 + kk] = s;
        }
        // reduce across dl (lane bits 2,3,4)
#pragma unroll
        for (int o = 4; o <= 16; o <<= 1) {
#pragma unroll
            for (int j = 0; j < 9; ++j)
                r[j] += __shfl_xor_sync(0xffffffffu, r[j], o);
        }
        if (dl == 0) {
            float* dst = red + ((size_t)dpanel * VT + vpanel * 32 + vl * 8 + i) * 9;
#pragma unroll
            for (int j = 0; j < 9; ++j) dst[j] = r[j];
        }
    }
    __syncthreads();

    if (tid < VT) {
        float acc[9];
#pragma unroll
        for (int j = 0; j < 9; ++j)
            acc[j] = red[(0 * VT + tid) * 9 + j] + red[(1 * VT + tid) * 9 + j]
                   + red[(2 * VT + tid) * 9 + j] + red[(3 * VT + tid) * 9 + j];
        float nrm = fmaxf(sqrtf(acc[0]), 1e-12f);
        float e[KCL];
        float esum = 0.f;
#pragma unroll
        for (int kk = 0; kk < KCL; ++kk) {
            float prob = acc[1 + kk] / nrm;
            e[kk] = expf(prob / 0.05f);
            esum += e[kk];
        }
        float* dst = g_soft + ((size_t)(b * NVV + v0 + tid)) * KCL;
#pragma unroll
        for (int kk = 0; kk < KCL; ++kk) dst[kk] = e[kk] / esum;
    }
}

// -------- kernel C: fused bernoulli + broadcast write ---------------------
// 2048 blocks x 32 contiguous rows (128KB contiguous stream per block).
#define ROWS_PER_BLK 32
__global__ __launch_bounds__(256, 8)
void write_kernel(float4* __restrict__ out) {
    __shared__ float vals[ROWS_PER_BLK];
    int rowbase = blockIdx.x * ROWS_PER_BLK;
    if (threadIdx.x < ROWS_PER_BLK) {
        int r = rowbase + threadIdx.x;             // (k,b,v) linear
        uint32_t bits = threefry_bits32(0u, (uint32_t)r);
        float f = __uint_as_float((bits >> 9) | 0x3f800000u) - 1.0f;
        float u = fmaxf(0.0f, f);
        int kk  = r >> 13;
        int rem = r & 8191;                        // b*512 + v
        vals[threadIdx.x] = (u < g_soft[rem * KCL + kk]) ? 1.0f : 0.0f;
    }
    __syncthreads();
    float4* o = out + (size_t)rowbase * 256 + threadIdx.x;
#pragma unroll
    for (int i = 0; i < ROWS_PER_BLK; ++i) {
        float v = vals[i];
        __stcs(&o[(size_t)i * 256], make_float4(v, v, v, v));
    }
}

// -------- launch -----------------------------------------------------------
extern "C" void kernel_launch(void* const* d_in, const int* in_sizes, int n_in,
                              void* d_out, int out_size) {
    const float* x = nullptr;
    const float* W = nullptr;
    const float* bias = nullptr;
    const float* ce = nullptr;
    for (int i = 0; i < n_in; ++i) {
        switch (in_sizes[i]) {
            case BSZ * SEQN * NVV: x    = (const float*)d_in[i]; break;
            case DMM * SEQN:       W    = (const float*)d_in[i]; break;
            case DMM:              bias = (const float*)d_in[i]; break;
            case KCL * DMM:        ce   = (const float*)d_in[i]; break;
            default: break;
        }
    }
    float4* out = (float4*)d_out;

    gemm_prob_kernel<<<dim3(NVV / VT, BSZ), 256>>>(x, W, bias, ce);
    write_kernel<<<(KCL * BSZ * NVV) / ROWS_PER_BLK, 256>>>(out);
    (void)out_size;
}